// round 6
// baseline (speedup 1.0000x reference)
#include <cuda_runtime.h>
#include <cuda_bf16.h>
#include <cstdint>

// Problem dims
#define TT 2048
#define BB 64
#define FFD 256
#define HH 256
#define NG 768  // 3*H

// Recurrence config: 16 clusters x 8 CTAs, 256 threads
#define CSZ 8
#define NCTA 128
#define NT 256

// -------- device scratch --------
__device__ float g_xi[(size_t)TT * BB * NG];     // 2048*64*768
__device__ float g_dump[(size_t)TT * BB * HH];   // fallback ys sink

// -------- packed f32x2 helpers --------
__device__ __forceinline__ void ffma2(unsigned long long& d, unsigned long long a, unsigned long long b) {
    asm volatile("fma.rn.f32x2 %0, %1, %2, %0;" : "+l"(d) : "l"(a), "l"(b));
}
__device__ __forceinline__ void add2(unsigned long long& d, unsigned long long a) {
    asm volatile("add.rn.f32x2 %0, %0, %1;" : "+l"(d) : "l"(a));
}
__device__ __forceinline__ unsigned long long dup2(float a) {
    unsigned long long d;
    asm("mov.b64 %0, {%1, %1};" : "=l"(d) : "f"(a));
    return d;
}
__device__ __forceinline__ unsigned long long pack2(float a, float b) {
    unsigned long long d;
    asm("mov.b64 %0, {%1, %2};" : "=l"(d) : "f"(a), "f"(b));
    return d;
}
__device__ __forceinline__ float2 unpack2(unsigned long long d) {
    float2 f;
    asm("mov.b64 {%0, %1}, %2;" : "=f"(f.x), "=f"(f.y) : "l"(d));
    return f;
}
__device__ __forceinline__ float tanh_ap(float x) {
    float y;
    asm("tanh.approx.f32 %0, %1;" : "=f"(y) : "f"(x));
    return y;
}
__device__ __forceinline__ float sigmoid_ap(float x) {
    return 0.5f * tanh_ap(0.5f * x) + 0.5f;
}
__device__ __forceinline__ uint32_t smem_u32(const void* p) {
    uint32_t a;
    asm("{ .reg .u64 t; cvta.to.shared.u64 t, %1; cvt.u32.u64 %0, t; }" : "=r"(a) : "l"(p));
    return a;
}
__device__ __forceinline__ void mbar_wait_cluster(uint32_t mbar, unsigned parity) {
    unsigned done = 0;
    do {
        asm volatile(
            "{ .reg .pred p; "
            "mbarrier.try_wait.parity.acquire.cluster.shared::cta.b64 p, [%1], %2, 0x989680; "
            "selp.b32 %0, 1, 0, p; }"
            : "=r"(done) : "r"(mbar), "r"(parity) : "memory");
    } while (!done);
}

// ============================================================
// Kernel 1: xi = xs @ Wi   (M=131072, K=256, N=768) — FFMA2 tiled
// ============================================================
__global__ __launch_bounds__(256, 2) void gemm_xi_kernel(const float* __restrict__ A,
                                                         const float* __restrict__ W) {
    __shared__ float As[16][132];
    __shared__ float Bs[16][128];
    const int tid = threadIdx.x;
    const int m0 = blockIdx.y * 128;
    const int n0 = blockIdx.x * 128;
    const int nt = tid & 15;
    const int mt = tid >> 4;

    unsigned long long acc[8][4];
#pragma unroll
    for (int i = 0; i < 8; i++)
#pragma unroll
        for (int j = 0; j < 4; j++) acc[i][j] = 0ULL;

    for (int kt = 0; kt < 256; kt += 16) {
#pragma unroll
        for (int i = 0; i < 2; i++) {
            int f4 = tid + i * 256;
            int row = f4 >> 2;
            int kq = (f4 & 3) << 2;
            float4 v = *(const float4*)(A + (size_t)(m0 + row) * 256 + kt + kq);
            As[kq + 0][row] = v.x; As[kq + 1][row] = v.y;
            As[kq + 2][row] = v.z; As[kq + 3][row] = v.w;
        }
#pragma unroll
        for (int i = 0; i < 2; i++) {
            int f4 = tid + i * 256;
            int row = f4 >> 5;
            int nq = (f4 & 31) << 2;
            float4 v = *(const float4*)(W + (size_t)(kt + row) * 768 + n0 + nq);
            *(float4*)&Bs[row][nq] = v;
        }
        __syncthreads();
#pragma unroll
        for (int k = 0; k < 16; k++) {
            float4 a0 = *(const float4*)&As[k][mt * 8];
            float4 a1 = *(const float4*)&As[k][mt * 8 + 4];
            ulonglong2 bA = *(const ulonglong2*)&Bs[k][nt * 8];
            ulonglong2 bB = *(const ulonglong2*)&Bs[k][nt * 8 + 4];
            float av[8] = {a0.x, a0.y, a0.z, a0.w, a1.x, a1.y, a1.z, a1.w};
#pragma unroll
            for (int i = 0; i < 8; i++) {
                unsigned long long ad = dup2(av[i]);
                ffma2(acc[i][0], ad, bA.x);
                ffma2(acc[i][1], ad, bA.y);
                ffma2(acc[i][2], ad, bB.x);
                ffma2(acc[i][3], ad, bB.y);
            }
        }
        __syncthreads();
    }
#pragma unroll
    for (int i = 0; i < 8; i++) {
        float2 c0 = unpack2(acc[i][0]);
        float2 c1 = unpack2(acc[i][1]);
        float2 c2 = unpack2(acc[i][2]);
        float2 c3 = unpack2(acc[i][3]);
        size_t off = (size_t)(m0 + mt * 8 + i) * 768 + n0 + nt * 8;
        *(float4*)(g_xi + off)     = make_float4(c0.x, c0.y, c1.x, c1.y);
        *(float4*)(g_xi + off + 4) = make_float4(c2.x, c2.y, c3.x, c3.y);
    }
}

// ============================================================
// Kernel 2: clustered GRU recurrence — weights in REGISTERS
// cluster (8 CTAs) = 4 batches; rank = 32 j-cols.
// Thread (kc, jp) holds w[16k][3g][2j] = 48 f32x2 regs for all 2048 steps.
// h exchange via DSMEM stores + per-CTA mbarrier arrive/wait.
// ============================================================

// smem float offsets
#define OFF_RED 0        // [256 threads][36]  partials
#define OFF_HT  9216     // [2][256 k][4 b]  double-buffered h
#define OFF_MB  11264    // 2 mbarriers (u64[2] = 4 floats)
#define SMEM_FLOATS 11272
#define SMEM_BYTES (SMEM_FLOATS * 4)

__global__ __launch_bounds__(NT, 1) __cluster_dims__(CSZ, 1, 1)
void gru_rec_kernel(const float* __restrict__ c,
                    const float* __restrict__ Wh,
                    const float* __restrict__ bh,
                    const float* __restrict__ b_in,
                    float* __restrict__ ys,
                    float* __restrict__ finalc) {
    extern __shared__ float sm[];
    float* sRED = sm + OFF_RED;
    float* sHT  = sm + OFF_HT;

    const int tid = threadIdx.x;
    uint32_t rank;
    asm("mov.u32 %0, %%cluster_ctarank;" : "=r"(rank));
    const int cid = blockIdx.x >> 3;          // cluster id 0..15 (batches 4cid..+3)

    const uint32_t mbase = smem_u32(sm + OFF_MB);   // mbar[buf] at mbase + buf*8

    // ---- init mbarriers (count = 8 arrivals: one per CTA in cluster) ----
    if (tid == 0) {
        asm volatile("mbarrier.init.shared.b64 [%0], %1;" :: "r"(mbase), "r"(8u) : "memory");
        asm volatile("mbarrier.init.shared.b64 [%0], %1;" :: "r"(mbase + 8), "r"(8u) : "memory");
    }

    // ---- phase-1 mapping + weight load into registers ----
    const int kc = tid >> 4;       // k-chunk 0..15 (16 k each)
    const int jp = tid & 15;       // j-pair 0..15 -> global j (rank*32 + 2jp, +1)
    const int j0w = (int)rank * 32 + jp * 2;

    unsigned long long wreg[48];   // [kk][g] f32x2 over j-pair
#pragma unroll
    for (int kk = 0; kk < 16; kk++) {
#pragma unroll
        for (int g = 0; g < 3; g++) {
            float2 w2 = __ldg((const float2*)(Wh + (size_t)(kc * 16 + kk) * 768 + g * 256 + j0w));
            wreg[kk * 3 + g] = pack2(w2.x, w2.y);
        }
    }

    // initial h into buf 0: sHT[0][k][b] = c[cid*4+b][k]
    for (int idx = tid; idx < 1024; idx += NT) {
        int k = idx >> 2;
        int b = idx & 3;
        sHT[k * 4 + b] = __ldg(c + (size_t)(cid * 4 + b) * 256 + k);
    }

    // gate mapping (tid < 64)
    const int jp_g = tid & 15;
    const int b_g = tid >> 4;                    // 0..3
    const int j0 = (int)rank * 32 + jp_g * 2;    // global j (even)
    const int b_glob = cid * 4 + (b_g & 3);

    float2 bhr2 = make_float2(0.f, 0.f), bhz2 = bhr2, bhn2 = bhr2, bin2 = bhr2;
    if (tid < 64) {
        bhr2 = __ldg((const float2*)(bh + j0));
        bhz2 = __ldg((const float2*)(bh + 256 + j0));
        bhn2 = __ldg((const float2*)(bh + 512 + j0));
        bin2 = __ldg((const float2*)(b_in + j0));
    }

    // remote sHT base addresses for all 8 ranks
    uint32_t ht_local = smem_u32(sHT);
    uint32_t rbase[CSZ];
#pragma unroll
    for (int r = 0; r < CSZ; r++) {
        asm("mapa.shared::cluster.u32 %0, %1, %2;" : "=r"(rbase[r]) : "r"(ht_local), "r"(r));
    }

    __syncthreads();
    // all CTAs' mbarriers + sHT buf0 ready before any peer traffic
    asm volatile("barrier.cluster.arrive.aligned;" ::: "memory");
    asm volatile("barrier.cluster.wait.aligned;" ::: "memory");

    // prefetch xi for t=0
    float2 xr2, xz2, xn2;
    if (tid < 64) {
        const float* xp = g_xi + (size_t)b_glob * 768 + j0;
        xr2 = __ldg((const float2*)xp);
        xz2 = __ldg((const float2*)(xp + 256));
        xn2 = __ldg((const float2*)(xp + 512));
    }

    int cur = 0;
    for (int t = 0; t < TT; t++) {
        const int nxt = cur ^ 1;

        // -- phase 1: register-weight GEMV partials --
        unsigned long long acc[3][4];
#pragma unroll
        for (int g = 0; g < 3; g++)
#pragma unroll
            for (int b = 0; b < 4; b++) acc[g][b] = 0ULL;
        {
            const float* hb = sHT + cur * 1024 + kc * 64;  // 16 k x 4 b
#pragma unroll
            for (int kk = 0; kk < 16; kk++) {
                float4 h4 = *(const float4*)(hb + kk * 4);   // broadcast LDS.128
                unsigned long long d0 = dup2(h4.x);
                unsigned long long d1 = dup2(h4.y);
                unsigned long long d2 = dup2(h4.z);
                unsigned long long d3 = dup2(h4.w);
                unsigned long long w0 = wreg[kk * 3 + 0];
                unsigned long long w1 = wreg[kk * 3 + 1];
                unsigned long long w2 = wreg[kk * 3 + 2];
                ffma2(acc[0][0], w0, d0); ffma2(acc[0][1], w0, d1);
                ffma2(acc[0][2], w0, d2); ffma2(acc[0][3], w0, d3);
                ffma2(acc[1][0], w1, d0); ffma2(acc[1][1], w1, d1);
                ffma2(acc[1][2], w1, d2); ffma2(acc[1][3], w1, d3);
                ffma2(acc[2][0], w2, d0); ffma2(acc[2][1], w2, d1);
                ffma2(acc[2][2], w2, d2); ffma2(acc[2][3], w2, d3);
            }
        }
        // write partials
        {
            float* rp = sRED + tid * 36;
#pragma unroll
            for (int b = 0; b < 4; b++) {
                ulonglong2 v;
                v.x = acc[0][b];
                v.y = acc[1][b];
                *(ulonglong2*)(rp + b * 8) = v;
                *(unsigned long long*)(rp + b * 8 + 4) = acc[2][b];
            }
        }
        __syncthreads();

        // -- phase 2+3: reduce + gates + exchange (64 threads) --
        if (tid < 64) {
            unsigned long long r2 = 0ULL, z2 = 0ULL, n2 = 0ULL;
            const float* rp0 = sRED + jp_g * 36 + b_g * 8;
#pragma unroll
            for (int q = 0; q < 16; q++) {
                const float* p = rp0 + q * (16 * 36);
                ulonglong2 v = *(const ulonglong2*)p;
                unsigned long long v2 = *(const unsigned long long*)(p + 4);
                add2(r2, v.x);
                add2(z2, v.y);
                add2(n2, v2);
            }
            float2 hr = unpack2(r2), hz = unpack2(z2), hn = unpack2(n2);
            float ho0 = sHT[cur * 1024 + j0 * 4 + b_g];
            float ho1 = sHT[cur * 1024 + (j0 + 1) * 4 + b_g];

            float r0 = sigmoid_ap(xr2.x + hr.x + bhr2.x);
            float r1 = sigmoid_ap(xr2.y + hr.y + bhr2.y);
            float z0 = sigmoid_ap(xz2.x + hz.x + bhz2.x);
            float z1 = sigmoid_ap(xz2.y + hz.y + bhz2.y);
            float n0 = tanh_ap(xn2.x + bin2.x + r0 * (hn.x + bhn2.x));
            float n1 = tanh_ap(xn2.y + bin2.y + r1 * (hn.y + bhn2.y));
            float h_new0 = (1.0f - z0) * n0 + z0 * ho0;
            float h_new1 = (1.0f - z1) * n1 + z1 * ho1;

            *(float2*)&ys[((size_t)t * 64 + b_glob) * 256 + j0] = make_float2(h_new0, h_new1);
            if (t == TT - 1)
                *(float2*)&finalc[(size_t)b_glob * 256 + j0] = make_float2(h_new0, h_new1);

            if (t + 1 < TT) {
                uint32_t off0 = (uint32_t)(nxt * 1024 + j0 * 4 + b_g) * 4u;
                uint32_t off1 = off0 + 16u;
#pragma unroll
                for (int r = 0; r < CSZ; r++) {
                    asm volatile("st.shared::cluster.f32 [%0], %1;" :: "r"(rbase[r] + off0), "f"(h_new0) : "memory");
                    asm volatile("st.shared::cluster.f32 [%0], %1;" :: "r"(rbase[r] + off1), "f"(h_new1) : "memory");
                }
            }
        }
        __syncthreads();

        if (t + 1 < TT) {
            // one release-arrive per destination CTA (cumulativity via the
            // __syncthreads above orders all gate-thread stores before it)
            if (tid < CSZ) {
                uint32_t ra;
                asm("mapa.shared::cluster.u32 %0, %1, %2;"
                    : "=r"(ra) : "r"(mbase + (uint32_t)nxt * 8u), "r"((uint32_t)tid));
                asm volatile("mbarrier.arrive.release.cluster.shared::cluster.b64 _, [%0];"
                             :: "r"(ra) : "memory");
            }
            // prefetch xi for t+1 before blocking
            if (tid < 64) {
                const float* xp = g_xi + ((size_t)(t + 1) * 64 + b_glob) * 768 + j0;
                xr2 = __ldg((const float2*)xp);
                xz2 = __ldg((const float2*)(xp + 256));
                xn2 = __ldg((const float2*)(xp + 512));
            }
            // wait for all 8 CTAs' h_new for buffer nxt
            mbar_wait_cluster(mbase + (uint32_t)nxt * 8u, (unsigned)((t >> 1) & 1));
        }
        cur = nxt;
    }

    // no CTA exits while peers might still touch its smem
    asm volatile("barrier.cluster.arrive.aligned;" ::: "memory");
    asm volatile("barrier.cluster.wait.aligned;" ::: "memory");
}

// ============================================================
extern "C" void kernel_launch(void* const* d_in, const int* in_sizes, int n_in,
                              void* d_out, int out_size) {
    const float* c    = (const float*)d_in[0];
    const float* xs   = (const float*)d_in[1];
    const float* Wi   = (const float*)d_in[2];
    const float* Wh   = (const float*)d_in[3];
    const float* bh   = (const float*)d_in[4];
    const float* b_in = (const float*)d_in[5];

    float* dmp;
    cudaGetSymbolAddress((void**)&dmp, g_dump);

    float* out = (float*)d_out;
    float* finalc;
    float* ys;
    const long long full = (long long)BB * HH + (long long)TT * BB * HH;
    if ((long long)out_size >= full) {
        finalc = out;            // tuple order: final_c first, then ys
        ys = out + BB * HH;
    } else if ((long long)out_size >= (long long)TT * BB * HH) {
        ys = out;
        finalc = dmp;
    } else {
        finalc = out;
        ys = dmp;
    }

    // 1) xi = xs @ Wi
    dim3 ggrid(NG / 128, (TT * BB) / 128);
    gemm_xi_kernel<<<ggrid, 256>>>(xs, Wi);
    // 2) clustered recurrence (weights in registers)
    gru_rec_kernel<<<NCTA, NT, SMEM_BYTES>>>(c, Wh, bh, b_in, ys, finalc);
}

// round 7
// speedup vs baseline: 1.3244x; 1.3244x over previous
#include <cuda_runtime.h>
#include <cuda_bf16.h>
#include <cstdint>

// Problem dims
#define TT 2048
#define BB 64
#define FFD 256
#define HH 256
#define NG 768  // 3*H

// Recurrence config: 16 clusters x 8 CTAs, 256 threads
#define CSZ 8
#define NCTA 128
#define NT 256

// -------- device scratch --------
__device__ float g_xi[(size_t)TT * BB * NG];     // 2048*64*768
__device__ float g_dump[(size_t)TT * BB * HH];   // fallback ys sink

// -------- packed f32x2 helpers --------
__device__ __forceinline__ void ffma2(unsigned long long& d, unsigned long long a, unsigned long long b) {
    asm volatile("fma.rn.f32x2 %0, %1, %2, %0;" : "+l"(d) : "l"(a), "l"(b));
}
__device__ __forceinline__ void add2(unsigned long long& d, unsigned long long a) {
    asm volatile("add.rn.f32x2 %0, %0, %1;" : "+l"(d) : "l"(a));
}
__device__ __forceinline__ unsigned long long dup2(float a) {
    unsigned long long d;
    asm("mov.b64 %0, {%1, %1};" : "=l"(d) : "f"(a));
    return d;
}
__device__ __forceinline__ unsigned long long pack2(float a, float b) {
    unsigned long long d;
    asm("mov.b64 %0, {%1, %2};" : "=l"(d) : "f"(a), "f"(b));
    return d;
}
__device__ __forceinline__ float2 unpack2(unsigned long long d) {
    float2 f;
    asm("mov.b64 {%0, %1}, %2;" : "=f"(f.x), "=f"(f.y) : "l"(d));
    return f;
}
__device__ __forceinline__ float tanh_ap(float x) {
    float y;
    asm("tanh.approx.f32 %0, %1;" : "=f"(y) : "f"(x));
    return y;
}
__device__ __forceinline__ float sigmoid_ap(float x) {
    return 0.5f * tanh_ap(0.5f * x) + 0.5f;
}
__device__ __forceinline__ uint32_t smem_u32(const void* p) {
    uint32_t a;
    asm("{ .reg .u64 t; cvta.to.shared.u64 t, %1; cvt.u32.u64 %0, t; }" : "=r"(a) : "l"(p));
    return a;
}
// CTA-scope wait: NO cluster-scope acquire -> no CCTL.IVALL on the poll loop.
__device__ __forceinline__ void mbar_wait_cta(uint32_t mbar, unsigned parity) {
    asm volatile(
        "{\n\t.reg .pred p;\n\t"
        "WAIT_%=:\n\t"
        "mbarrier.try_wait.parity.acquire.cta.shared::cta.b64 p, [%0], %1, 0x989680;\n\t"
        "@!p bra WAIT_%=;\n\t}"
        :: "r"(mbar), "r"(parity) : "memory");
}
// Remote tx-tracked store: data + completion bytes to peer CTA, no fence needed.
__device__ __forceinline__ void st_async_f32(uint32_t daddr, float v, uint32_t maddr) {
    asm volatile(
        "st.async.shared::cluster.mbarrier::complete_tx::bytes.b32 [%0], %1, [%2];"
        :: "r"(daddr), "r"(__float_as_uint(v)), "r"(maddr) : "memory");
}

// ============================================================
// Kernel 1: xi = xs @ Wi   (M=131072, K=256, N=768) — FFMA2 tiled
// ============================================================
__global__ __launch_bounds__(256, 2) void gemm_xi_kernel(const float* __restrict__ A,
                                                         const float* __restrict__ W) {
    __shared__ float As[16][132];
    __shared__ float Bs[16][128];
    const int tid = threadIdx.x;
    const int m0 = blockIdx.y * 128;
    const int n0 = blockIdx.x * 128;
    const int nt = tid & 15;
    const int mt = tid >> 4;

    unsigned long long acc[8][4];
#pragma unroll
    for (int i = 0; i < 8; i++)
#pragma unroll
        for (int j = 0; j < 4; j++) acc[i][j] = 0ULL;

    for (int kt = 0; kt < 256; kt += 16) {
#pragma unroll
        for (int i = 0; i < 2; i++) {
            int f4 = tid + i * 256;
            int row = f4 >> 2;
            int kq = (f4 & 3) << 2;
            float4 v = *(const float4*)(A + (size_t)(m0 + row) * 256 + kt + kq);
            As[kq + 0][row] = v.x; As[kq + 1][row] = v.y;
            As[kq + 2][row] = v.z; As[kq + 3][row] = v.w;
        }
#pragma unroll
        for (int i = 0; i < 2; i++) {
            int f4 = tid + i * 256;
            int row = f4 >> 5;
            int nq = (f4 & 31) << 2;
            float4 v = *(const float4*)(W + (size_t)(kt + row) * 768 + n0 + nq);
            *(float4*)&Bs[row][nq] = v;
        }
        __syncthreads();
#pragma unroll
        for (int k = 0; k < 16; k++) {
            float4 a0 = *(const float4*)&As[k][mt * 8];
            float4 a1 = *(const float4*)&As[k][mt * 8 + 4];
            ulonglong2 bA = *(const ulonglong2*)&Bs[k][nt * 8];
            ulonglong2 bB = *(const ulonglong2*)&Bs[k][nt * 8 + 4];
            float av[8] = {a0.x, a0.y, a0.z, a0.w, a1.x, a1.y, a1.z, a1.w};
#pragma unroll
            for (int i = 0; i < 8; i++) {
                unsigned long long ad = dup2(av[i]);
                ffma2(acc[i][0], ad, bA.x);
                ffma2(acc[i][1], ad, bA.y);
                ffma2(acc[i][2], ad, bB.x);
                ffma2(acc[i][3], ad, bB.y);
            }
        }
        __syncthreads();
    }
#pragma unroll
    for (int i = 0; i < 8; i++) {
        float2 c0 = unpack2(acc[i][0]);
        float2 c1 = unpack2(acc[i][1]);
        float2 c2 = unpack2(acc[i][2]);
        float2 c3 = unpack2(acc[i][3]);
        size_t off = (size_t)(m0 + mt * 8 + i) * 768 + n0 + nt * 8;
        *(float4*)(g_xi + off)     = make_float4(c0.x, c0.y, c1.x, c1.y);
        *(float4*)(g_xi + off + 4) = make_float4(c2.x, c2.y, c3.x, c3.y);
    }
}

// ============================================================
// Kernel 2: clustered GRU recurrence — register weights + st.async exchange
// cluster (8 CTAs) = 4 batches; rank = 32 j-cols.
// Per step: GEMV partials -> smem reduce -> gates -> st.async h_new to all
// ranks (tx-tracked) -> expect_tx/acquire.cta wait. No cluster-scope fences.
// ============================================================

// smem float offsets
#define OFF_RED 0        // [256 threads][36]  partials
#define OFF_HT  9216     // [2][256 k][4 b]  double-buffered h
#define OFF_MB  11264    // 2 mbarriers (2 x u64)
#define SMEM_FLOATS 11272
#define SMEM_BYTES (SMEM_FLOATS * 4)

#define TX_BYTES 4096u   // 8 ranks x 64 threads x 2 floats x 4B into each CTA

__global__ __launch_bounds__(NT, 1) __cluster_dims__(CSZ, 1, 1)
void gru_rec_kernel(const float* __restrict__ c,
                    const float* __restrict__ Wh,
                    const float* __restrict__ bh,
                    const float* __restrict__ b_in,
                    float* __restrict__ ys,
                    float* __restrict__ finalc) {
    extern __shared__ float sm[];
    float* sRED = sm + OFF_RED;
    float* sHT  = sm + OFF_HT;

    const int tid = threadIdx.x;
    uint32_t rank;
    asm("mov.u32 %0, %%cluster_ctarank;" : "=r"(rank));
    const int cid = blockIdx.x >> 3;          // cluster id 0..15 (batches 4cid..+3)

    const uint32_t mbase = smem_u32(sm + OFF_MB);   // mbar[buf] at mbase + buf*8

    // ---- init mbarriers (count = 1: the local expect_tx arrival) ----
    if (tid == 0) {
        asm volatile("mbarrier.init.shared.b64 [%0], %1;" :: "r"(mbase), "r"(1u) : "memory");
        asm volatile("mbarrier.init.shared.b64 [%0], %1;" :: "r"(mbase + 8), "r"(1u) : "memory");
        // expect for the FIRST exchange (step 0 writes buffer 1 via mb[1])
        asm volatile("mbarrier.arrive.expect_tx.shared.b64 _, [%0], %1;"
                     :: "r"(mbase + 8), "r"(TX_BYTES) : "memory");
    }

    // ---- phase-1 mapping + weight load into registers ----
    const int kc = tid >> 4;       // k-chunk 0..15 (16 k each)
    const int jp = tid & 15;       // j-pair 0..15 -> global j (rank*32 + 2jp, +1)
    const int j0w = (int)rank * 32 + jp * 2;

    unsigned long long wreg[48];   // [kk][g] f32x2 over j-pair
#pragma unroll
    for (int kk = 0; kk < 16; kk++) {
#pragma unroll
        for (int g = 0; g < 3; g++) {
            float2 w2 = __ldg((const float2*)(Wh + (size_t)(kc * 16 + kk) * 768 + g * 256 + j0w));
            wreg[kk * 3 + g] = pack2(w2.x, w2.y);
        }
    }

    // initial h into buf 0: sHT[0][k][b] = c[cid*4+b][k]
    for (int idx = tid; idx < 1024; idx += NT) {
        int k = idx >> 2;
        int b = idx & 3;
        sHT[k * 4 + b] = __ldg(c + (size_t)(cid * 4 + b) * 256 + k);
    }

    // gate mapping (tid < 64)
    const int jp_g = tid & 15;
    const int b_g = tid >> 4;                    // 0..3
    const int j0 = (int)rank * 32 + jp_g * 2;    // global j (even)
    const int b_glob = cid * 4 + (b_g & 3);

    float2 bhr2 = make_float2(0.f, 0.f), bhz2 = bhr2, bhn2 = bhr2, bin2 = bhr2;
    if (tid < 64) {
        bhr2 = __ldg((const float2*)(bh + j0));
        bhz2 = __ldg((const float2*)(bh + 256 + j0));
        bhn2 = __ldg((const float2*)(bh + 512 + j0));
        bin2 = __ldg((const float2*)(b_in + j0));
    }

    // remote addresses for all 8 ranks: sHT data base + both mbarriers
    uint32_t ht_local = smem_u32(sHT);
    uint32_t rdata[CSZ], rmb0[CSZ], rmb1[CSZ];
#pragma unroll
    for (int r = 0; r < CSZ; r++) {
        asm("mapa.shared::cluster.u32 %0, %1, %2;" : "=r"(rdata[r]) : "r"(ht_local), "r"(r));
        asm("mapa.shared::cluster.u32 %0, %1, %2;" : "=r"(rmb0[r]) : "r"(mbase), "r"(r));
        asm("mapa.shared::cluster.u32 %0, %1, %2;" : "=r"(rmb1[r]) : "r"(mbase + 8u), "r"(r));
    }

    __syncthreads();
    // all CTAs' mbarriers + expect + sHT buf0 ready before any peer traffic
    asm volatile("barrier.cluster.arrive.aligned;" ::: "memory");
    asm volatile("barrier.cluster.wait.aligned;" ::: "memory");

    // prefetch xi for t=0
    float2 xr2, xz2, xn2;
    if (tid < 64) {
        const float* xp = g_xi + (size_t)b_glob * 768 + j0;
        xr2 = __ldg((const float2*)xp);
        xz2 = __ldg((const float2*)(xp + 256));
        xn2 = __ldg((const float2*)(xp + 512));
    }

    unsigned ph0 = 0, ph1 = 0;   // parity trackers for mb[0], mb[1]
    int cur = 0;
    for (int t = 0; t < TT; t++) {
        const int nxt = cur ^ 1;

        // -- phase 1: register-weight GEMV partials --
        unsigned long long acc[3][4];
#pragma unroll
        for (int g = 0; g < 3; g++)
#pragma unroll
            for (int b = 0; b < 4; b++) acc[g][b] = 0ULL;
        {
            const float* hb = sHT + cur * 1024 + kc * 64;  // 16 k x 4 b
#pragma unroll
            for (int kk = 0; kk < 16; kk++) {
                float4 h4 = *(const float4*)(hb + kk * 4);   // broadcast LDS.128
                unsigned long long d0 = dup2(h4.x);
                unsigned long long d1 = dup2(h4.y);
                unsigned long long d2 = dup2(h4.z);
                unsigned long long d3 = dup2(h4.w);
                unsigned long long w0 = wreg[kk * 3 + 0];
                unsigned long long w1 = wreg[kk * 3 + 1];
                unsigned long long w2 = wreg[kk * 3 + 2];
                ffma2(acc[0][0], w0, d0); ffma2(acc[0][1], w0, d1);
                ffma2(acc[0][2], w0, d2); ffma2(acc[0][3], w0, d3);
                ffma2(acc[1][0], w1, d0); ffma2(acc[1][1], w1, d1);
                ffma2(acc[1][2], w1, d2); ffma2(acc[1][3], w1, d3);
                ffma2(acc[2][0], w2, d0); ffma2(acc[2][1], w2, d1);
                ffma2(acc[2][2], w2, d2); ffma2(acc[2][3], w2, d3);
            }
        }
        // write partials
        {
            float* rp = sRED + tid * 36;
#pragma unroll
            for (int b = 0; b < 4; b++) {
                ulonglong2 v;
                v.x = acc[0][b];
                v.y = acc[1][b];
                *(ulonglong2*)(rp + b * 8) = v;
                *(unsigned long long*)(rp + b * 8 + 4) = acc[2][b];
            }
        }
        __syncthreads();

        // post expect_tx for the exchange at step t+1 (uses mb[cur]); one
        // non-gate thread so gate threads aren't delayed. Safe: mb[cur]'s
        // previous phase completed at the end of step t-1.
        if (tid == 64 && t + 2 < TT) {
            uint32_t mb = mbase + (uint32_t)cur * 8u;
            asm volatile("mbarrier.arrive.expect_tx.shared.b64 _, [%0], %1;"
                         :: "r"(mb), "r"(TX_BYTES) : "memory");
        }

        // -- phase 2+3: reduce + gates + exchange (64 threads) --
        if (tid < 64) {
            unsigned long long r2 = 0ULL, z2 = 0ULL, n2 = 0ULL;
            const float* rp0 = sRED + jp_g * 36 + b_g * 8;
#pragma unroll
            for (int q = 0; q < 16; q++) {
                const float* p = rp0 + q * (16 * 36);
                ulonglong2 v = *(const ulonglong2*)p;
                unsigned long long v2 = *(const unsigned long long*)(p + 4);
                add2(r2, v.x);
                add2(z2, v.y);
                add2(n2, v2);
            }
            float2 hr = unpack2(r2), hz = unpack2(z2), hn = unpack2(n2);
            float ho0 = sHT[cur * 1024 + j0 * 4 + b_g];
            float ho1 = sHT[cur * 1024 + (j0 + 1) * 4 + b_g];

            float r0 = sigmoid_ap(xr2.x + hr.x + bhr2.x);
            float r1 = sigmoid_ap(xr2.y + hr.y + bhr2.y);
            float z0 = sigmoid_ap(xz2.x + hz.x + bhz2.x);
            float z1 = sigmoid_ap(xz2.y + hz.y + bhz2.y);
            float n0 = tanh_ap(xn2.x + bin2.x + r0 * (hn.x + bhn2.x));
            float n1 = tanh_ap(xn2.y + bin2.y + r1 * (hn.y + bhn2.y));
            float h_new0 = (1.0f - z0) * n0 + z0 * ho0;
            float h_new1 = (1.0f - z1) * n1 + z1 * ho1;

            *(float2*)&ys[((size_t)t * 64 + b_glob) * 256 + j0] = make_float2(h_new0, h_new1);
            if (t == TT - 1)
                *(float2*)&finalc[(size_t)b_glob * 256 + j0] = make_float2(h_new0, h_new1);

            if (t + 1 < TT) {
                // tx-tracked remote stores into every rank's sHT[nxt][j][b]
                uint32_t off0 = (uint32_t)(nxt * 1024 + j0 * 4 + b_g) * 4u;
                uint32_t off1 = off0 + 16u;
#pragma unroll
                for (int r = 0; r < CSZ; r++) {
                    uint32_t mb = (nxt ? rmb1[r] : rmb0[r]);
                    st_async_f32(rdata[r] + off0, h_new0, mb);
                    st_async_f32(rdata[r] + off1, h_new1, mb);
                }
            }
        }

        if (t + 1 < TT) {
            // prefetch xi for t+1 before blocking
            if (tid < 64) {
                const float* xp = g_xi + ((size_t)(t + 1) * 64 + b_glob) * 768 + j0;
                xr2 = __ldg((const float2*)xp);
                xz2 = __ldg((const float2*)(xp + 256));
                xn2 = __ldg((const float2*)(xp + 512));
            }
            // wait for all 8 CTAs' h_new bytes for buffer nxt (cta-scope acquire)
            if (nxt) { mbar_wait_cta(mbase + 8u, ph1); ph1 ^= 1; }
            else     { mbar_wait_cta(mbase,      ph0); ph0 ^= 1; }
        }
        cur = nxt;
    }

    // no CTA exits while peers might still reference its smem
    asm volatile("barrier.cluster.arrive.aligned;" ::: "memory");
    asm volatile("barrier.cluster.wait.aligned;" ::: "memory");
}

// ============================================================
extern "C" void kernel_launch(void* const* d_in, const int* in_sizes, int n_in,
                              void* d_out, int out_size) {
    const float* c    = (const float*)d_in[0];
    const float* xs   = (const float*)d_in[1];
    const float* Wi   = (const float*)d_in[2];
    const float* Wh   = (const float*)d_in[3];
    const float* bh   = (const float*)d_in[4];
    const float* b_in = (const float*)d_in[5];

    float* dmp;
    cudaGetSymbolAddress((void**)&dmp, g_dump);

    float* out = (float*)d_out;
    float* finalc;
    float* ys;
    const long long full = (long long)BB * HH + (long long)TT * BB * HH;
    if ((long long)out_size >= full) {
        finalc = out;            // tuple order: final_c first, then ys
        ys = out + BB * HH;
    } else if ((long long)out_size >= (long long)TT * BB * HH) {
        ys = out;
        finalc = dmp;
    } else {
        finalc = out;
        ys = dmp;
    }

    // 1) xi = xs @ Wi
    dim3 ggrid(NG / 128, (TT * BB) / 128);
    gemm_xi_kernel<<<ggrid, 256>>>(xs, Wi);
    // 2) clustered recurrence (register weights + st.async exchange)
    gru_rec_kernel<<<NCTA, NT, SMEM_BYTES>>>(c, Wh, bh, b_in, ys, finalc);
}